// round 13
// baseline (speedup 1.0000x reference)
#include <cuda_runtime.h>
#include <cuda_fp16.h>
#include <math.h>

#define BATCH 512
#define TT    256
#define DD    32
#define HH    256
#define M_TOTAL (BATCH*TT)
#define PSTR  (BATCH*4*TT*64)

// scan config: 16 clusters x 8 CTAs, 32 rows/cluster, 32 neurons/CTA
#define CL   8
#define RPB  32
#define K0T  19
#define K1T  32
#define KFT  16
#define SA   1080    // act row stride (halves): x32|pd|pad15|h1b0 256|h1b1 256|h2b0 256|h2b1 256
#define GSTR 33
#define XS   264
#define QS   72
#define FS   136

// ---------------- static device scratch ----------------
__device__ __half W0f[K0T*64*256];
__device__ __half W1f[K1T*64*256];
__device__ __half WFf[KFT*16*256];
__device__ __half WinpH[768*256];
__device__ __half WfinH[256*512];
__device__ float  b1fw[256];
__device__ __half Lgh[M_TOTAL*HH];
__device__ __half CTXh[M_TOTAL*HH];
__device__ float  QKVg[3*PSTR];

__device__ __forceinline__ float sigf(float x) { return 1.f / (1.f + __expf(-x)); }
__device__ __forceinline__ float tanh_f(float x) {
    x = fmaxf(fminf(x, 30.f), -30.f);
    float z = __expf(-2.f * x);
    return (1.f - z) / (1.f + z);
}
__device__ __forceinline__ void ldsm4(unsigned &r0, unsigned &r1, unsigned &r2, unsigned &r3, unsigned addr) {
    asm volatile("ldmatrix.sync.aligned.m8n8.x4.shared.b16 {%0,%1,%2,%3}, [%4];"
                 : "=r"(r0),"=r"(r1),"=r"(r2),"=r"(r3) : "r"(addr));
}
__device__ __forceinline__ void ldsm2(unsigned &r0, unsigned &r1, unsigned addr) {
    asm volatile("ldmatrix.sync.aligned.m8n8.x2.shared.b16 {%0,%1}, [%2];"
                 : "=r"(r0),"=r"(r1) : "r"(addr));
}
__device__ __forceinline__ void mma_op(float* c, unsigned a0, unsigned a1, unsigned a2, unsigned a3,
                                       unsigned b0, unsigned b1) {
    asm volatile("mma.sync.aligned.m16n8k16.row.col.f32.f16.f16.f32 "
        "{%0,%1,%2,%3}, {%4,%5,%6,%7}, {%8,%9}, {%0,%1,%2,%3};"
        : "+f"(c[0]), "+f"(c[1]), "+f"(c[2]), "+f"(c[3])
        : "r"(a0), "r"(a1), "r"(a2), "r"(a3), "r"(b0), "r"(b1));
}
__device__ __forceinline__ unsigned pack_h2(float a, float b) {
    __half2 h = __floats2half2_rn(a, b);
    return *(unsigned*)&h;
}
__device__ __forceinline__ void cluster_sync_() {
    asm volatile("barrier.cluster.arrive.aligned;\n\tbarrier.cluster.wait.aligned;" ::: "memory");
}
__device__ __forceinline__ void st_cluster_u32(unsigned laddr, unsigned rank, unsigned val) {
    unsigned ra;
    asm volatile("mapa.shared::cluster.u32 %0, %1, %2;" : "=r"(ra) : "r"(laddr), "r"(rank));
    asm volatile("st.shared::cluster.u32 [%0], %1;" :: "r"(ra), "r"(val) : "memory");
}

// ---------------- prep (unchanged, verified) ----------------
__global__ void prep_frag(const float* __restrict__ Wih0, const float* __restrict__ Whh0,
                          const float* __restrict__ Wih1, const float* __restrict__ Whh1,
                          const float* __restrict__ W1,   const float* __restrict__ Winp) {
    int i = blockIdx.x * 256 + threadIdx.x;
    const int E0 = K0T*64*256;
    const int E1 = E0 + K1T*64*256;
    const int E2 = E1 + KFT*16*256;
    const int E3 = E2 + 768*256;
    const int E4 = E3 + 65536;
    if (i < E0) {
        int q = i & 7, lane = (i >> 3) & 31, tile = i >> 8;
        int mt = tile / K0T, kt = tile - mt * K0T;
        int r = lane >> 2, c = lane & 3;
        int dm = r + ((q >> 1) & 1) * 8;
        int dk = 2*c + (q & 1) + ((q >= 4) ? 8 : 0);
        int m = mt*16 + dm, k = kt*16 + dk;
        float v = 0.f;
        if (k < 33) v = Wih0[m*33 + k];
        else if (k >= 48) v = Whh0[m*256 + (k - 48)];
        W0f[i] = __float2half(v);
    } else if (i < E1) {
        int e = i - E0;
        int q = e & 7, lane = (e >> 3) & 31, tile = e >> 8;
        int mt = tile >> 5, kt = tile & 31;
        int r = lane >> 2, c = lane & 3;
        int dm = r + ((q >> 1) & 1) * 8;
        int dk = 2*c + (q & 1) + ((q >= 4) ? 8 : 0);
        int m = mt*16 + dm, k = kt*16 + dk;
        float v = (k < 256) ? Wih1[m*256 + k] : Whh1[m*256 + (k - 256)];
        W1f[e] = __float2half(v);
    } else if (i < E2) {
        int e = i - E1;
        int q = e & 7, lane = (e >> 3) & 31, tile = e >> 8;
        int mt = tile >> 4, kt = tile & 15;
        int r = lane >> 2, c = lane & 3;
        int dm = r + ((q >> 1) & 1) * 8;
        int dk = 2*c + (q & 1) + ((q >= 4) ? 8 : 0);
        int m = mt*16 + dm, k = kt*16 + dk;
        WFf[e] = __float2half(W1[m*512 + k] + W1[m*512 + 256 + k]);
    } else if (i < E3) {
        int e = i - E2;
        WinpH[e] = __float2half(Winp[e]);
    } else if (i < E4) {
        int e = i - E3; int r = e >> 8, k = e & 255;
        WfinH[r*512 + k] = __float2half(W1[r*512 + k]);
    }
}

__global__ void prep_wcomb(const float* __restrict__ W1, const float* __restrict__ Wop) {
    int r = blockIdx.x, m = threadIdx.x;
    float s = 0.f;
    for (int k = 0; k < 256; k++) s += W1[r*512 + 256 + k] * Wop[k*256 + m];
    WfinH[r*512 + 256 + m] = __float2half(s);
}

__global__ void prep_b1f(const float* __restrict__ b1, const float* __restrict__ bop,
                         const float* __restrict__ W1) {
    int r = threadIdx.x;
    float s = b1[r];
    for (int k = 0; k < 256; k++) s += bop[k] * W1[r*512 + 256 + k];
    b1fw[r] = s;
}

// ---------------- scan warp GEMM, N=32 (R12-verified math) ----------------
template<int KT, int SPLIT>
__device__ __forceinline__ void gemm_warp32(const __half* __restrict__ Wg, int mtA, int mtC,
                                            unsigned actb, int bstr, unsigned extra,
                                            float* __restrict__ gs, int lane) {
    const int r = lane >> 2, c2 = (lane & 3) * 2;
    float acc[4][4];
#pragma unroll
    for (int nt = 0; nt < 4; nt++)
#pragma unroll
        for (int i = 0; i < 4; i++) acc[nt][i] = 0.f;
    const uint4* Ap = (const uint4*)Wg + (size_t)mtA*KT*32 + lane;
    const int brow = (lane & 7) + ((lane >> 4) << 3);
    const int bkoff = ((lane >> 3) & 1) * 8;
    const unsigned baddr0 = actb + (unsigned)((brow*bstr + bkoff) * 2);
    const unsigned baddr1 = baddr0 + (unsigned)(16*bstr*2);
#pragma unroll
    for (int kt = 0; kt < KT; kt++) {
        uint4 A = Ap[kt*32];
        unsigned ext = (kt >= SPLIT) ? extra : 0u;
        unsigned b00,b01,b10,b11,b20,b21,b30,b31;
        ldsm4(b00,b01,b10,b11, baddr0 + (unsigned)(kt*32) + ext);
        ldsm4(b20,b21,b30,b31, baddr1 + (unsigned)(kt*32) + ext);
        mma_op(acc[0], A.x,A.y,A.z,A.w, b00,b01);
        mma_op(acc[1], A.x,A.y,A.z,A.w, b10,b11);
        mma_op(acc[2], A.x,A.y,A.z,A.w, b20,b21);
        mma_op(acc[3], A.x,A.y,A.z,A.w, b30,b31);
    }
    const int m0 = mtC*16;
    float* g0 = gs + (m0 + r)*GSTR + c2;
    float* g1 = gs + (m0 + 8 + r)*GSTR + c2;
#pragma unroll
    for (int nt = 0; nt < 4; nt++) {
        g0[nt*8]     = acc[nt][0]; g0[nt*8 + 1] = acc[nt][1];
        g1[nt*8]     = acc[nt][2]; g1[nt*8 + 1] = acc[nt][3];
    }
}

// ---------------- clustered scan: 128 CTAs (16 clusters x 8), 256 thr ----------------
extern __shared__ char smem_raw[];

__global__ void __launch_bounds__(256, 1) __cluster_dims__(CL, 1, 1)
scan_kernel(const float* __restrict__ F,
            const float* __restrict__ bih0, const float* __restrict__ bhh0,
            const float* __restrict__ bih1, const float* __restrict__ bhh1,
            const float* __restrict__ b1, const float* __restrict__ W2,
            const float* __restrict__ b2p)
{
    __half* act  = (__half*)smem_raw;                   // 32*1080*2 = 69120
    float*  gs   = (float*)(smem_raw + 69120);          // 128*33*4  = 16896
    float*  red  = (float*)(smem_raw + 86016);          // 8*32*4    = 1024
    float*  pdex = (float*)(smem_raw + 87040);          // 8*32*4    = 1024  -> 88064

    const int tid = threadIdx.x;
    const int w = tid >> 5, lane = tid & 31;
    unsigned crank; asm("mov.u32 %0, %%cluster_ctarank;" : "=r"(crank));
    const int b0r = (blockIdx.x >> 3) * RPB;

    const unsigned a_b  = (unsigned)__cvta_generic_to_shared(act);
    const unsigned pd_b = (unsigned)__cvta_generic_to_shared(pdex);

    // gemm m-tiles: warp w covers gate (w>>1), neuron-half (w&1)
    const int mt01 = (w >> 1)*16 + (int)crank*2 + (w & 1);
    // activation role: neurons {n2, n2+1}, rows {rr, rr+16}
    const int n2 = (tid & 15) * 2;
    const int rr = tid >> 4;
    const int ng = (int)crank*32 + n2;

    float bi0[2][4], bi1[2][4];
#pragma unroll
    for (int j = 0; j < 2; j++)
#pragma unroll
        for (int g = 0; g < 4; g++) {
            bi0[j][g] = bih0[g*256 + ng + j] + bhh0[g*256 + ng + j];
            bi1[j][g] = bih1[g*256 + ng + j] + bhh1[g*256 + ng + j];
        }
    // fc reduce role: row = tid&31, units w*4+[0,4)
    float w2v[4], b1v[4];
#pragma unroll
    for (int j = 0; j < 4; j++) {
        int gu = (int)crank*32 + w*4 + j;
        w2v[j] = W2[gu]; b1v[j] = b1[gu];
    }
    const float b2v = b2p[0];
    float c1v[2][2] = {{0.f,0.f},{0.f,0.f}};
    float c2v[2][2] = {{0.f,0.f},{0.f,0.f}};

    const __half hz = __float2half(0.f);
    for (int i = tid; i < RPB*SA; i += 256) act[i] = hz;
    cluster_sync_();

    for (int t = 0; t < TT; t++) {
        const int hb = t & 1;
        const unsigned ext0 = (unsigned)(((t + 1) & 1) * 512);     // L0: h1 read buffer
        const unsigned ext1 = (unsigned)(1024 - hb*1024);          // L1: h2 read buffer adjust
        const unsigned base1 = a_b + (unsigned)((48 + hb*256) * 2);
        const unsigned baseF = a_b + (unsigned)((560 + hb*256) * 2);

        // stage x: 32 rows x 32, 4 per thread
#pragma unroll
        for (int i = 0; i < 4; i++) {
            int idx = tid + i*256;
            int row = idx >> 5, kx = idx & 31;
            act[row*SA + kx] = __float2half(F[(size_t)(b0r + row)*(TT*DD) + t*DD + kx]);
        }
        __syncthreads();

        gemm_warp32<K0T, 3>(W0f, mt01, w, a_b, SA, ext0, gs, lane);
        __syncthreads();

        // L0 activation
#pragma unroll
        for (int r2 = 0; r2 < 2; r2++) {
            int row = rr + r2*16;
            float h1p[2];
#pragma unroll
            for (int j = 0; j < 2; j++) {
                float gi = gs[(     n2 + j)*GSTR + row] + bi0[j][0];
                float gf = gs[(32 + n2 + j)*GSTR + row] + bi0[j][1];
                float gG = gs[(64 + n2 + j)*GSTR + row] + bi0[j][2];
                float go = gs[(96 + n2 + j)*GSTR + row] + bi0[j][3];
                c1v[r2][j] = sigf(gf)*c1v[r2][j] + sigf(gi)*tanh_f(gG);
                h1p[j] = sigf(go)*tanh_f(c1v[r2][j]);
            }
            unsigned hv = pack_h2(h1p[0], h1p[1]);
            unsigned off = a_b + (unsigned)((row*SA + 48 + hb*256 + ng) * 2);
#pragma unroll
            for (unsigned rk = 0; rk < CL; rk++) st_cluster_u32(off, rk, hv);
        }
        cluster_sync_();

        gemm_warp32<K1T, 16>(W1f, mt01, w, base1, SA, ext1, gs, lane);
        __syncthreads();

        // L1 activation + Lgh
#pragma unroll
        for (int r2 = 0; r2 < 2; r2++) {
            int row = rr + r2*16;
            float h2p[2];
#pragma unroll
            for (int j = 0; j < 2; j++) {
                float gi = gs[(     n2 + j)*GSTR + row] + bi1[j][0];
                float gf = gs[(32 + n2 + j)*GSTR + row] + bi1[j][1];
                float gG = gs[(64 + n2 + j)*GSTR + row] + bi1[j][2];
                float go = gs[(96 + n2 + j)*GSTR + row] + bi1[j][3];
                c2v[r2][j] = sigf(gf)*c2v[r2][j] + sigf(gi)*tanh_f(gG);
                h2p[j] = sigf(go)*tanh_f(c2v[r2][j]);
            }
            unsigned hv = pack_h2(h2p[0], h2p[1]);
            unsigned off = a_b + (unsigned)((row*SA + 560 + hb*256 + ng) * 2);
#pragma unroll
            for (unsigned rk = 0; rk < CL; rk++) st_cluster_u32(off, rk, hv);
            *(unsigned*)&Lgh[(size_t)(b0r + row)*(TT*HH) + (size_t)t*HH + ng] = hv;
        }
        cluster_sync_();

        // FC: warps 0,1 compute this CTA's 32 hidden units over 32 rows
        if (w < 2)
            gemm_warp32<KFT, 99>(WFf, (int)crank*2 + w, w, baseF, SA, 0u, gs, lane);
        __syncthreads();

        // pd partial: thread(row=tid&31, units w*4+[0,4))
        {
            int r = tid & 31;
            float v = 0.f;
#pragma unroll
            for (int j = 0; j < 4; j++)
                v += w2v[j] * fmaxf(gs[(w*4 + j)*GSTR + r] + b1v[j], 0.f);
            red[w*32 + r] = v;
        }
        __syncthreads();
        if (tid < 32) {
            float p = 0.f;
#pragma unroll
            for (int g = 0; g < 8; g++) p += red[g*32 + tid];
            unsigned off = pd_b + (unsigned)(((int)crank*32 + tid) * 4);
            unsigned pv = __float_as_uint(p);
#pragma unroll
            for (unsigned rk = 0; rk < CL; rk++) st_cluster_u32(off, rk, pv);
        }
        cluster_sync_();
        if (tid < 32) {
            float s = b2v;
#pragma unroll
            for (int k = 0; k < 8; k++) s += pdex[k*32 + tid];
            act[tid*SA + 32] = __float2half(s);
        }
        // next loop's post-staging __syncthreads orders pd before L0 gemm
    }
}

// ---------------- qkv HMMA GEMM (verified) ----------------
__global__ void __launch_bounds__(256) qkv_hmma(const float* __restrict__ binp) {
    extern __shared__ char sm[];
    __half* Xs  = (__half*)sm;
    __half* Wsh = (__half*)(sm + 128*XS*2);
    const int m0 = blockIdx.x * 128;
    const int n0 = blockIdx.y * 64;
    const int tid = threadIdx.x, w = tid >> 5, lane = tid & 31;

    {
        const uint4* src = (const uint4*)(Lgh + (size_t)m0*256);
#pragma unroll
        for (int i = 0; i < 16; i++) {
            int idx = tid + i*256;
            int row = idx >> 5, q = idx & 31;
            *(uint4*)(Xs + row*XS + q*8) = src[row*32 + q];
        }
        const uint4* wsrc = (const uint4*)(WinpH + (size_t)n0*256);
#pragma unroll
        for (int i = 0; i < 8; i++) {
            int idx = tid + i*256;
            int row = idx >> 5, q = idx & 31;
            *(uint4*)(Wsh + row*XS + q*8) = wsrc[row*32 + q];
        }
    }
    __syncthreads();

    float acc[8][4];
#pragma unroll
    for (int i = 0; i < 8; i++)
#pragma unroll
        for (int j = 0; j < 4; j++) acc[i][j] = 0.f;

    const int arow = (lane & 7) + (((lane >> 3) & 1) << 3);
    const int akoff = ((lane >> 4) & 1) * 8;
    const unsigned abase = (unsigned)__cvta_generic_to_shared(Xs)
                         + (unsigned)(((w*16 + arow)*XS + akoff)*2);
    const unsigned bbase = (unsigned)__cvta_generic_to_shared(Wsh)
                         + (unsigned)((((lane & 7)*XS) + ((lane >> 3) & 1)*8)*2);

#pragma unroll
    for (int kt = 0; kt < 16; kt++) {
        unsigned a0,a1,a2,a3;
        ldsm4(a0,a1,a2,a3, abase + kt*32);
#pragma unroll
        for (int nt = 0; nt < 8; nt++) {
            unsigned b0,b1;
            ldsm2(b0,b1, bbase + (unsigned)(nt*8*XS*2) + kt*32);
            mma_op(acc[nt], a0,a1,a2,a3, b0,b1);
        }
    }

    const int r = lane >> 2, c = lane & 3;
    const int m1 = m0 + w*16 + r, m2 = m1 + 8;
    const int bb1 = m1 >> 8, tt1 = m1 & 255;
    const int bb2 = m2 >> 8, tt2 = m2 & 255;
#pragma unroll
    for (int nt = 0; nt < 8; nt++) {
        int nn = n0 + nt*8 + 2*c;
        float bi0 = binp[nn], bi1 = binp[nn+1];
        int part = nn >> 8, head = (nn >> 6) & 3, d = nn & 63;
        float* d1 = QKVg + ((size_t)((part*BATCH + bb1)*4 + head)*TT + tt1)*64 + d;
        float* d2 = QKVg + ((size_t)((part*BATCH + bb2)*4 + head)*TT + tt2)*64 + d;
        float2 v1; v1.x = acc[nt][0]+bi0; v1.y = acc[nt][1]+bi1;
        float2 v2; v2.x = acc[nt][2]+bi0; v2.y = acc[nt][3]+bi1;
        *(float2*)d1 = v1;
        *(float2*)d2 = v2;
    }
}

// ---------------- attention HMMA (verified) ----------------
__global__ void __launch_bounds__(256, 1) attn_hmma() {
    extern __shared__ char sm[];
    __half* Qs = (__half*)sm;
    __half* Ks = (__half*)(sm + 36864);
    __half* Vt = (__half*)(sm + 46080);
    const int b = blockIdx.x, h = blockIdx.y;
    const int tid = threadIdx.x, w = tid >> 5, lane = tid & 31;
    const float* Qb = QKVg + ((size_t)(b*4 + h))*TT*64;
    const float* Kb = Qb + PSTR;
    const float* Vb = Kb + PSTR;

#pragma unroll
    for (int i = 0; i < 16; i++) {
        int idx = tid + i*256;
        int row = idx >> 4, d4 = idx & 15;
        float4 v = *(const float4*)&Qb[(size_t)row*64 + d4*4];
        unsigned u01 = pack_h2(v.x, v.y), u23 = pack_h2(v.z, v.w);
        *(unsigned*)&Qs[row*QS + d4*4]     = u01;
        *(unsigned*)&Qs[row*QS + d4*4 + 2] = u23;
    }
    __syncthreads();

    const int arow = (lane & 7) + (((lane >> 3) & 1) << 3);
    const int akoff = ((lane >> 4) & 1) * 8;
    unsigned aQ[2][4][4];
#pragma unroll
    for (int mt = 0; mt < 2; mt++) {
        unsigned abase = (unsigned)__cvta_generic_to_shared(Qs)
                       + (unsigned)(((w*32 + mt*16 + arow)*QS + akoff)*2);
#pragma unroll
        for (int kt = 0; kt < 4; kt++)
            ldsm4(aQ[mt][kt][0], aQ[mt][kt][1], aQ[mt][kt][2], aQ[mt][kt][3], abase + kt*32);
    }

    const unsigned bK = (unsigned)__cvta_generic_to_shared(Ks)
                      + (unsigned)((((lane & 7)*QS) + ((lane >> 3) & 1)*8)*2);
    const unsigned bV = (unsigned)__cvta_generic_to_shared(Vt)
                      + (unsigned)((((lane & 7)*QS) + ((lane >> 3) & 1)*8)*2);

    float oacc[2][8][4];
#pragma unroll
    for (int mt = 0; mt < 2; mt++)
#pragma unroll
        for (int nt = 0; nt < 8; nt++)
#pragma unroll
            for (int i = 0; i < 4; i++) oacc[mt][nt][i] = 0.f;
    float rs[2][2] = {{0.f,0.f},{0.f,0.f}};

    for (int kc = 0; kc < 4; kc++) {
#pragma unroll
        for (int i = 0; i < 4; i++) {
            int idx = tid + i*256;
            int row = idx >> 4, d4 = idx & 15;
            float4 v = *(const float4*)&Kb[(size_t)(kc*64 + row)*64 + d4*4];
            unsigned u01 = pack_h2(v.x, v.y), u23 = pack_h2(v.z, v.w);
            *(unsigned*)&Ks[row*QS + d4*4]     = u01;
            *(unsigned*)&Ks[row*QS + d4*4 + 2] = u23;
        }
#pragma unroll
        for (int i = 0; i < 16; i++) {
            int idx = tid + i*256;
            int key = idx >> 6, d = idx & 63;
            Vt[d*QS + key] = __float2half(Vb[(size_t)(kc*64 + key)*64 + d]);
        }
        __syncthreads();

        float sc[2][8][4];
#pragma unroll
        for (int mt = 0; mt < 2; mt++)
#pragma unroll
            for (int nt = 0; nt < 8; nt++)
#pragma unroll
                for (int i = 0; i < 4; i++) sc[mt][nt][i] = 0.f;
#pragma unroll
        for (int kt = 0; kt < 4; kt++) {
#pragma unroll
            for (int nt = 0; nt < 8; nt++) {
                unsigned b0, b1;
                ldsm2(b0, b1, bK + (unsigned)(nt*8*QS*2) + kt*32);
                mma_op(sc[0][nt], aQ[0][kt][0], aQ[0][kt][1], aQ[0][kt][2], aQ[0][kt][3], b0, b1);
                mma_op(sc[1][nt], aQ[1][kt][0], aQ[1][kt][1], aQ[1][kt][2], aQ[1][kt][3], b0, b1);
            }
        }

#pragma unroll
        for (int mt = 0; mt < 2; mt++)
#pragma unroll
            for (int nt = 0; nt < 8; nt++) {
                float p0 = __expf(sc[mt][nt][0] * 0.125f);
                float p1 = __expf(sc[mt][nt][1] * 0.125f);
                float p2 = __expf(sc[mt][nt][2] * 0.125f);
                float p3 = __expf(sc[mt][nt][3] * 0.125f);
                rs[mt][0] += p0 + p1;
                rs[mt][1] += p2 + p3;
                sc[mt][nt][0] = p0; sc[mt][nt][1] = p1;
                sc[mt][nt][2] = p2; sc[mt][nt][3] = p3;
            }

#pragma unroll
        for (int kt2 = 0; kt2 < 4; kt2++) {
            unsigned aP[2][4];
#pragma unroll
            for (int mt = 0; mt < 2; mt++) {
                aP[mt][0] = pack_h2(sc[mt][2*kt2][0],   sc[mt][2*kt2][1]);
                aP[mt][1] = pack_h2(sc[mt][2*kt2][2],   sc[mt][2*kt2][3]);
                aP[mt][2] = pack_h2(sc[mt][2*kt2+1][0], sc[mt][2*kt2+1][1]);
                aP[mt][3] = pack_h2(sc[mt][2*kt2+1][2], sc[mt][2*kt2+1][3]);
            }
#pragma unroll
            for (int nt = 0; nt < 8; nt++) {
                unsigned b0, b1;
                ldsm2(b0, b1, bV + (unsigned)(nt*8*QS*2) + kt2*32);
                mma_op(oacc[0][nt], aP[0][0], aP[0][1], aP[0][2], aP[0][3], b0, b1);
                mma_op(oacc[1][nt], aP[1][0], aP[1][1], aP[1][2], aP[1][3], b0, b1);
            }
        }
        __syncthreads();
    }

#pragma unroll
    for (int mt = 0; mt < 2; mt++)
#pragma unroll
        for (int j = 0; j < 2; j++) {
            rs[mt][j] += __shfl_xor_sync(0xffffffffu, rs[mt][j], 1);
            rs[mt][j] += __shfl_xor_sync(0xffffffffu, rs[mt][j], 2);
        }

    const int r = lane >> 2, c = lane & 3;
#pragma unroll
    for (int mt = 0; mt < 2; mt++) {
        float inv0 = 1.f / rs[mt][0];
        float inv1 = 1.f / rs[mt][1];
        int row0 = w*32 + mt*16 + r;
        int row1 = row0 + 8;
#pragma unroll
        for (int nt = 0; nt < 8; nt++) {
            int col = h*64 + nt*8 + 2*c;
            *(unsigned*)&CTXh[((size_t)(b*TT + row0))*HH + col] =
                pack_h2(oacc[mt][nt][0]*inv0, oacc[mt][nt][1]*inv0);
            *(unsigned*)&CTXh[((size_t)(b*TT + row1))*HH + col] =
                pack_h2(oacc[mt][nt][2]*inv1, oacc[mt][nt][3]*inv1);
        }
    }
}

// ---------------- final HMMA (verified) ----------------
__global__ void __launch_bounds__(256) final_hmma(const float* __restrict__ W2,
                                                  const float* __restrict__ b2p,
                                                  float* __restrict__ out) {
    extern __shared__ char sm[];
    __half* Xs   = (__half*)sm;
    __half* Wsm  = (__half*)(sm + 32*FS*2);
    float*  redm = (float*)(sm + 32*FS*2 + 256*FS*2);
    const int m0 = blockIdx.x * 32;
    const int tid = threadIdx.x, w = tid >> 5, lane = tid & 31;
    const int mt = w >> 2, nq = w & 3;

    float acc[8][4];
#pragma unroll
    for (int i = 0; i < 8; i++)
#pragma unroll
        for (int j = 0; j < 4; j++) acc[i][j] = 0.f;

    const int arow = (lane & 7) + (((lane >> 3) & 1) << 3);
    const int akoff = ((lane >> 4) & 1) * 8;
    const unsigned abase = (unsigned)__cvta_generic_to_shared(Xs)
                         + (unsigned)(((mt*16 + arow)*FS + akoff)*2);
    const unsigned bbase = (unsigned)__cvta_generic_to_shared(Wsm)
                         + (unsigned)((((nq*64 + (lane & 7))*FS) + ((lane >> 3) & 1)*8)*2);

    for (int ch = 0; ch < 4; ch++) {
        const __half* xsrc = (ch < 2) ? Lgh : CTXh;
        int kc = (ch & 1) * 128;
#pragma unroll
        for (int i = 0; i < 2; i++) {
            int idx = tid + i*256;
            int row = idx >> 4, q = idx & 15;
            *(uint4*)(Xs + row*FS + q*8) =
                *(const uint4*)(xsrc + (size_t)(m0+row)*256 + kc + q*8);
        }
#pragma unroll
        for (int i = 0; i < 16; i++) {
            int idx = tid + i*256;
            int row = idx >> 4, q = idx & 15;
            *(uint4*)(Wsm + row*FS + q*8) =
                *(const uint4*)(WfinH + (size_t)row*512 + ch*128 + q*8);
        }
        __syncthreads();
#pragma unroll
        for (int kt = 0; kt < 8; kt++) {
            unsigned a0,a1,a2,a3;
            ldsm4(a0,a1,a2,a3, abase + kt*32);
#pragma unroll
            for (int nt = 0; nt < 8; nt++) {
                unsigned b0,b1;
                ldsm2(b0,b1, bbase + (unsigned)(nt*8*FS*2) + kt*32);
                mma_op(acc[nt], a0,a1,a2,a3, b0,b1);
            }
        }
        __syncthreads();
    }

    const int r = lane >> 2, c = lane & 3;
    float s0 = 0.f, s1 = 0.f;
#pragma unroll
    for (int nt = 0; nt < 8; nt++) {
        int nn = nq*64 + nt*8 + 2*c;
        float bb0 = b1fw[nn], bb1v = b1fw[nn+1];
        float w20 = W2[nn],   w21 = W2[nn+1];
        s0 += w20*fmaxf(acc[nt][0] + bb0, 0.f) + w21*fmaxf(acc[nt][1] + bb1v, 0.f);
        s1 += w20*fmaxf(acc[nt][2] + bb0, 0.f) + w21*fmaxf(acc[nt][3] + bb1v, 0.f);
    }
    s0 += __shfl_xor_sync(0xffffffffu, s0, 1);
    s0 += __shfl_xor_sync(0xffffffffu, s0, 2);
    s1 += __shfl_xor_sync(0xffffffffu, s1, 1);
    s1 += __shfl_xor_sync(0xffffffffu, s1, 2);
    if ((lane & 3) == 0) {
        redm[nq*32 + mt*16 + r]     = s0;
        redm[nq*32 + mt*16 + 8 + r] = s1;
    }
    __syncthreads();
    if (tid < 32)
        out[m0 + tid] = b2p[0] + redm[tid] + redm[32 + tid] + redm[64 + tid] + redm[96 + tid];
}

// ---------------- launch ----------------
extern "C" void kernel_launch(void* const* d_in, const int* in_sizes, int n_in,
                              void* d_out, int out_size) {
    (void)in_sizes; (void)n_in; (void)out_size;
    const float* F     = (const float*)d_in[0];
    const float* Wih0  = (const float*)d_in[1];
    const float* Whh0  = (const float*)d_in[2];
    const float* bih0  = (const float*)d_in[3];
    const float* bhh0  = (const float*)d_in[4];
    const float* Wih1  = (const float*)d_in[5];
    const float* Whh1  = (const float*)d_in[6];
    const float* bih1  = (const float*)d_in[7];
    const float* bhh1  = (const float*)d_in[8];
    const float* Winp  = (const float*)d_in[9];
    const float* binp  = (const float*)d_in[10];
    const float* Wop   = (const float*)d_in[11];
    const float* bop   = (const float*)d_in[12];
    const float* W1    = (const float*)d_in[13];
    const float* b1    = (const float*)d_in[14];
    const float* W2    = (const float*)d_in[15];
    const float* b2    = (const float*)d_in[16];
    float* out = (float*)d_out;

    const int SCAN_SMEM = 88064;
    const int QKV_SMEM  = (128*XS + 64*XS)*2;
    const int ATT_SMEM  = 256*QS*2 + 64*QS*2 + 64*QS*2;
    const int FIN_SMEM  = (32*FS + 256*FS)*2 + 4*32*4;
    cudaFuncSetAttribute(scan_kernel, cudaFuncAttributeMaxDynamicSharedMemorySize, SCAN_SMEM);
    cudaFuncSetAttribute(qkv_hmma,    cudaFuncAttributeMaxDynamicSharedMemorySize, QKV_SMEM);
    cudaFuncSetAttribute(attn_hmma,   cudaFuncAttributeMaxDynamicSharedMemorySize, ATT_SMEM);
    cudaFuncSetAttribute(final_hmma,  cudaFuncAttributeMaxDynamicSharedMemorySize, FIN_SMEM);

    prep_frag<<<4544, 256>>>(Wih0, Whh0, Wih1, Whh1, W1, Winp);
    prep_wcomb<<<256, 256>>>(W1, Wop);
    prep_b1f<<<1, 256>>>(b1, bop, W1);
    scan_kernel<<<128, 256, SCAN_SMEM>>>(F, bih0, bhh0, bih1, bhh1, b1, W2, b2);
    qkv_hmma<<<dim3(1024, 12), 256, QKV_SMEM>>>(binp);
    attn_hmma<<<dim3(512, 4), 256, ATT_SMEM>>>();
    final_hmma<<<4096, 256, FIN_SMEM>>>(W2, b2, out);
}

// round 14
// speedup vs baseline: 1.8447x; 1.8447x over previous
#include <cuda_runtime.h>
#include <cuda_fp16.h>
#include <math.h>

#define BATCH 512
#define TT    256
#define DD    32
#define HH    256
#define M_TOTAL (BATCH*TT)
#define PSTR  (BATCH*4*TT*64)

// scan config: 32 clusters x 4 CTAs, 16 rows/cluster, 64 neurons/CTA (R11 topology)
#define CL   4
#define RPB  16
#define K0T  19
#define K1T  32
#define KFT  16
#define SA   1080    // act row stride (halves): x32|pd|pad15|h1b0|h1b1|h2b0|h2b1
#define GSTR 17
#define XS   264
#define QS   72
#define FS   136

// ---------------- static device scratch ----------------
__device__ __half W0f[K0T*64*256];
__device__ __half W1f[K1T*64*256];
__device__ __half WFf[KFT*16*256];
__device__ __half WinpH[768*256];
__device__ __half WfinH[256*512];
__device__ float  b1fw[256];
__device__ __half Lgh[M_TOTAL*HH];
__device__ __half CTXh[M_TOTAL*HH];
__device__ __half QKVh[3*PSTR];

__device__ __forceinline__ float sigf(float x) { return 1.f / (1.f + __expf(-x)); }
__device__ __forceinline__ float tanh_f(float x) {
    x = fmaxf(fminf(x, 30.f), -30.f);
    float z = __expf(-2.f * x);
    return (1.f - z) / (1.f + z);
}
__device__ __forceinline__ void ldsm4(unsigned &r0, unsigned &r1, unsigned &r2, unsigned &r3, unsigned addr) {
    asm volatile("ldmatrix.sync.aligned.m8n8.x4.shared.b16 {%0,%1,%2,%3}, [%4];"
                 : "=r"(r0),"=r"(r1),"=r"(r2),"=r"(r3) : "r"(addr));
}
__device__ __forceinline__ void ldsm2(unsigned &r0, unsigned &r1, unsigned addr) {
    asm volatile("ldmatrix.sync.aligned.m8n8.x2.shared.b16 {%0,%1}, [%2];"
                 : "=r"(r0),"=r"(r1) : "r"(addr));
}
__device__ __forceinline__ void mma_op(float* c, unsigned a0, unsigned a1, unsigned a2, unsigned a3,
                                       unsigned b0, unsigned b1) {
    asm volatile("mma.sync.aligned.m16n8k16.row.col.f32.f16.f16.f32 "
        "{%0,%1,%2,%3}, {%4,%5,%6,%7}, {%8,%9}, {%0,%1,%2,%3};"
        : "+f"(c[0]), "+f"(c[1]), "+f"(c[2]), "+f"(c[3])
        : "r"(a0), "r"(a1), "r"(a2), "r"(a3), "r"(b0), "r"(b1));
}
__device__ __forceinline__ unsigned pack_h2(float a, float b) {
    __half2 h = __floats2half2_rn(a, b);
    return *(unsigned*)&h;
}
__device__ __forceinline__ void cluster_sync_() {
    asm volatile("barrier.cluster.arrive.aligned;\n\tbarrier.cluster.wait.aligned;" ::: "memory");
}
__device__ __forceinline__ void st_cluster_u32(unsigned laddr, unsigned rank, unsigned val) {
    unsigned ra;
    asm volatile("mapa.shared::cluster.u32 %0, %1, %2;" : "=r"(ra) : "r"(laddr), "r"(rank));
    asm volatile("st.shared::cluster.u32 [%0], %1;" :: "r"(ra), "r"(val) : "memory");
}

// ---------------- prep (verified) ----------------
__global__ void prep_frag(const float* __restrict__ Wih0, const float* __restrict__ Whh0,
                          const float* __restrict__ Wih1, const float* __restrict__ Whh1,
                          const float* __restrict__ W1,   const float* __restrict__ Winp) {
    int i = blockIdx.x * 256 + threadIdx.x;
    const int E0 = K0T*64*256;
    const int E1 = E0 + K1T*64*256;
    const int E2 = E1 + KFT*16*256;
    const int E3 = E2 + 768*256;
    const int E4 = E3 + 65536;
    if (i < E0) {
        int q = i & 7, lane = (i >> 3) & 31, tile = i >> 8;
        int mt = tile / K0T, kt = tile - mt * K0T;
        int r = lane >> 2, c = lane & 3;
        int dm = r + ((q >> 1) & 1) * 8;
        int dk = 2*c + (q & 1) + ((q >= 4) ? 8 : 0);
        int m = mt*16 + dm, k = kt*16 + dk;
        float v = 0.f;
        if (k < 33) v = Wih0[m*33 + k];
        else if (k >= 48) v = Whh0[m*256 + (k - 48)];
        W0f[i] = __float2half(v);
    } else if (i < E1) {
        int e = i - E0;
        int q = e & 7, lane = (e >> 3) & 31, tile = e >> 8;
        int mt = tile >> 5, kt = tile & 31;
        int r = lane >> 2, c = lane & 3;
        int dm = r + ((q >> 1) & 1) * 8;
        int dk = 2*c + (q & 1) + ((q >= 4) ? 8 : 0);
        int m = mt*16 + dm, k = kt*16 + dk;
        float v = (k < 256) ? Wih1[m*256 + k] : Whh1[m*256 + (k - 256)];
        W1f[e] = __float2half(v);
    } else if (i < E2) {
        int e = i - E1;
        int q = e & 7, lane = (e >> 3) & 31, tile = e >> 8;
        int mt = tile >> 4, kt = tile & 15;
        int r = lane >> 2, c = lane & 3;
        int dm = r + ((q >> 1) & 1) * 8;
        int dk = 2*c + (q & 1) + ((q >= 4) ? 8 : 0);
        int m = mt*16 + dm, k = kt*16 + dk;
        WFf[e] = __float2half(W1[m*512 + k] + W1[m*512 + 256 + k]);
    } else if (i < E3) {
        int e = i - E2;
        WinpH[e] = __float2half(Winp[e]);
    } else if (i < E4) {
        int e = i - E3; int r = e >> 8, k = e & 255;
        WfinH[r*512 + k] = __float2half(W1[r*512 + k]);
    }
}

__global__ void prep_wcomb(const float* __restrict__ W1, const float* __restrict__ Wop) {
    int r = blockIdx.x, m = threadIdx.x;
    float s = 0.f;
    for (int k = 0; k < 256; k++) s += W1[r*512 + 256 + k] * Wop[k*256 + m];
    WfinH[r*512 + 256 + m] = __float2half(s);
}

__global__ void prep_b1f(const float* __restrict__ b1, const float* __restrict__ bop,
                         const float* __restrict__ W1) {
    int r = threadIdx.x;
    float s = b1[r];
    for (int k = 0; k < 256; k++) s += bop[k] * W1[r*512 + 256 + k];
    b1fw[r] = s;
}

// ---------------- scan warp GEMM, N=16 (R11 math + R13-verified split addressing) ----------------
template<int KT, int SPLIT>
__device__ __forceinline__ void gemm_warp(const __half* __restrict__ Wg, int mtA, int mtC,
                                          unsigned actb, int bstr, unsigned extra,
                                          float* __restrict__ gs, int lane) {
    const int r = lane >> 2, c2 = (lane & 3) * 2;
    float acc0[4] = {0.f,0.f,0.f,0.f};
    float acc1[4] = {0.f,0.f,0.f,0.f};
    const uint4* Ap = (const uint4*)Wg + (size_t)mtA*KT*32 + lane;
    const int brow = (lane & 7) + ((lane >> 4) << 3);
    const int bkoff = ((lane >> 3) & 1) * 8;
    const unsigned baddr = actb + (unsigned)((brow*bstr + bkoff) * 2);
#pragma unroll
    for (int kt = 0; kt < KT; kt++) {
        uint4 A = Ap[kt*32];
        unsigned b00, b01, b10, b11;
        unsigned addr = baddr + (unsigned)(kt*32) + ((kt >= SPLIT) ? extra : 0u);
        ldsm4(b00, b01, b10, b11, addr);
        mma_op(acc0, A.x, A.y, A.z, A.w, b00, b01);
        mma_op(acc1, A.x, A.y, A.z, A.w, b10, b11);
    }
    const int m0 = mtC*16;
    float* g0 = gs + (m0 + r)*GSTR + c2;
    float* g1 = gs + (m0 + 8 + r)*GSTR + c2;
    g0[0] = acc0[0]; g0[1] = acc0[1];
    g1[0] = acc0[2]; g1[1] = acc0[3];
    g0[8] = acc1[0]; g0[9] = acc1[1];
    g1[8] = acc1[2]; g1[9] = acc1[3];
}

// ---------------- clustered scan: 128 CTAs (32 clusters x 4), 512 thr, unified act ----------------
extern __shared__ char smem_raw[];

__global__ void __launch_bounds__(512, 1) __cluster_dims__(CL, 1, 1)
scan_kernel(const float* __restrict__ F,
            const float* __restrict__ bih0, const float* __restrict__ bhh0,
            const float* __restrict__ bih1, const float* __restrict__ bhh1,
            const float* __restrict__ b1, const float* __restrict__ W2,
            const float* __restrict__ b2p)
{
    __half* act = (__half*)smem_raw;                 // 16*1080*2 = 34560
    float*  gs  = (float*)(smem_raw + 34560);        // 256*17*4  = 17408 -> 51968

    const int tid = threadIdx.x;
    const int w = tid >> 5, lane = tid & 31;
    unsigned crank; asm("mov.u32 %0, %%cluster_ctarank;" : "=r"(crank));
    const int b0r = (blockIdx.x >> 2) * RPB;
    const int nbase = (int)crank * 64;
    const int ar = w;
    const int u  = lane * 2;
    const int ng = nbase + u;

    const unsigned a_b = (unsigned)__cvta_generic_to_shared(act);

    const int gq = w >> 2, qq = w & 3;
    const int mtA01 = gq*16 + (int)crank*4 + qq;

    float bi0[2][4], bi1[2][4];
#pragma unroll
    for (int j = 0; j < 2; j++)
#pragma unroll
        for (int g = 0; g < 4; g++) {
            bi0[j][g] = bih0[g*256 + ng + j] + bhh0[g*256 + ng + j];
            bi1[j][g] = bih1[g*256 + ng + j] + bhh1[g*256 + ng + j];
        }
    float w2v[8], b1v[8];
#pragma unroll
    for (int i = 0; i < 8; i++) { w2v[i] = W2[lane + 32*i]; b1v[i] = b1[lane + 32*i]; }
    const float b2v = b2p[0];
    float c1v[2] = {0.f, 0.f}, c2v[2] = {0.f, 0.f};

    const __half hz = __float2half(0.f);
    for (int i = tid; i < RPB*SA; i += 512) act[i] = hz;
    cluster_sync_();

    for (int t = 0; t < TT; t++) {
        const int hb = t & 1;
        const unsigned ext0 = (unsigned)(((t + 1) & 1) * 512);   // L0 h1 read buffer
        const unsigned ext1 = (unsigned)(1024 - hb*1024);        // L1 h2 read buffer delta
        const unsigned base1 = a_b + (unsigned)((48 + hb*256) * 2);
        const unsigned baseF = a_b + (unsigned)((560 + hb*256) * 2);

        // stage x: 16 rows x 32 vals, 1 per thread
        {
            int row = tid >> 5, kx = tid & 31;
            act[row*SA + kx] = __float2half(F[(size_t)(b0r + row)*(TT*DD) + t*DD + kx]);
        }
        __syncthreads();

        gemm_warp<K0T, 3>(W0f, mtA01, w, a_b, SA, ext0, gs, lane);
        __syncthreads();

        // L0 activation (row ar, neurons u,u+1); single h1 broadcast
        {
            float h1p[2];
#pragma unroll
            for (int j = 0; j < 2; j++) {
                float gi = gs[(      u + j)*GSTR + ar] + bi0[j][0];
                float gf = gs[( 64 + u + j)*GSTR + ar] + bi0[j][1];
                float gG = gs[(128 + u + j)*GSTR + ar] + bi0[j][2];
                float go = gs[(192 + u + j)*GSTR + ar] + bi0[j][3];
                c1v[j] = sigf(gf)*c1v[j] + sigf(gi)*tanh_f(gG);
                h1p[j] = sigf(go)*tanh_f(c1v[j]);
            }
            unsigned hv = pack_h2(h1p[0], h1p[1]);
            unsigned off = a_b + (unsigned)((ar*SA + 48 + hb*256 + ng) * 2);
#pragma unroll
            for (unsigned rk = 0; rk < CL; rk++) st_cluster_u32(off, rk, hv);
        }
        cluster_sync_();

        gemm_warp<K1T, 16>(W1f, mtA01, w, base1, SA, ext1, gs, lane);
        __syncthreads();

        // L1 activation + Lgh
        {
            float h2p[2];
#pragma unroll
            for (int j = 0; j < 2; j++) {
                float gi = gs[(      u + j)*GSTR + ar] + bi1[j][0];
                float gf = gs[( 64 + u + j)*GSTR + ar] + bi1[j][1];
                float gG = gs[(128 + u + j)*GSTR + ar] + bi1[j][2];
                float go = gs[(192 + u + j)*GSTR + ar] + bi1[j][3];
                c2v[j] = sigf(gf)*c2v[j] + sigf(gi)*tanh_f(gG);
                h2p[j] = sigf(go)*tanh_f(c2v[j]);
            }
            unsigned hv = pack_h2(h2p[0], h2p[1]);
            unsigned off = a_b + (unsigned)((ar*SA + 560 + hb*256 + ng) * 2);
#pragma unroll
            for (unsigned rk = 0; rk < CL; rk++) st_cluster_u32(off, rk, hv);
            *(unsigned*)&Lgh[(size_t)(b0r + ar)*(TT*HH) + (size_t)t*HH + ng] = hv;
        }
        cluster_sync_();

        // FC (full 256 hidden units per CTA, redundant across cluster)
        gemm_warp<KFT, 99>(WFf, w, w, baseF, SA, 0u, gs, lane);
        __syncthreads();

        // pd reduce: warp ar covers all 256 hidden units
        {
            float v = 0.f;
#pragma unroll
            for (int i = 0; i < 8; i++)
                v += w2v[i] * fmaxf(gs[(lane + 32*i)*GSTR + ar] + b1v[i], 0.f);
#pragma unroll
            for (int off = 16; off > 0; off >>= 1)
                v += __shfl_down_sync(0xffffffffu, v, off);
            if (lane == 0) act[ar*SA + 32] = __float2half(v + b2v);
        }
        // next iteration's post-staging __syncthreads orders pd before L0 gemm
    }
}

// ---------------- qkv HMMA GEMM, fp16 output ----------------
__global__ void __launch_bounds__(256) qkv_hmma(const float* __restrict__ binp) {
    extern __shared__ char sm[];
    __half* Xs  = (__half*)sm;
    __half* Wsh = (__half*)(sm + 128*XS*2);
    const int m0 = blockIdx.x * 128;
    const int n0 = blockIdx.y * 64;
    const int tid = threadIdx.x, w = tid >> 5, lane = tid & 31;

    {
        const uint4* src = (const uint4*)(Lgh + (size_t)m0*256);
#pragma unroll
        for (int i = 0; i < 16; i++) {
            int idx = tid + i*256;
            int row = idx >> 5, q = idx & 31;
            *(uint4*)(Xs + row*XS + q*8) = src[row*32 + q];
        }
        const uint4* wsrc = (const uint4*)(WinpH + (size_t)n0*256);
#pragma unroll
        for (int i = 0; i < 8; i++) {
            int idx = tid + i*256;
            int row = idx >> 5, q = idx & 31;
            *(uint4*)(Wsh + row*XS + q*8) = wsrc[row*32 + q];
        }
    }
    __syncthreads();

    float acc[8][4];
#pragma unroll
    for (int i = 0; i < 8; i++)
#pragma unroll
        for (int j = 0; j < 4; j++) acc[i][j] = 0.f;

    const int arow = (lane & 7) + (((lane >> 3) & 1) << 3);
    const int akoff = ((lane >> 4) & 1) * 8;
    const unsigned abase = (unsigned)__cvta_generic_to_shared(Xs)
                         + (unsigned)(((w*16 + arow)*XS + akoff)*2);
    const unsigned bbase = (unsigned)__cvta_generic_to_shared(Wsh)
                         + (unsigned)((((lane & 7)*XS) + ((lane >> 3) & 1)*8)*2);

#pragma unroll
    for (int kt = 0; kt < 16; kt++) {
        unsigned a0,a1,a2,a3;
        ldsm4(a0,a1,a2,a3, abase + kt*32);
#pragma unroll
        for (int nt = 0; nt < 8; nt++) {
            unsigned b0,b1;
            ldsm2(b0,b1, bbase + (unsigned)(nt*8*XS*2) + kt*32);
            mma_op(acc[nt], a0,a1,a2,a3, b0,b1);
        }
    }

    const int r = lane >> 2, c = lane & 3;
    const int m1 = m0 + w*16 + r, m2 = m1 + 8;
    const int bb1 = m1 >> 8, tt1 = m1 & 255;
    const int bb2 = m2 >> 8, tt2 = m2 & 255;
#pragma unroll
    for (int nt = 0; nt < 8; nt++) {
        int nn = n0 + nt*8 + 2*c;
        float bi0 = binp[nn], bi1 = binp[nn+1];
        int part = nn >> 8, head = (nn >> 6) & 3, d = nn & 63;
        __half* d1 = QKVh + ((size_t)((part*BATCH + bb1)*4 + head)*TT + tt1)*64 + d;
        __half* d2 = QKVh + ((size_t)((part*BATCH + bb2)*4 + head)*TT + tt2)*64 + d;
        *(unsigned*)d1 = pack_h2(acc[nt][0]+bi0, acc[nt][1]+bi1);
        *(unsigned*)d2 = pack_h2(acc[nt][2]+bi0, acc[nt][3]+bi1);
    }
}

// ---------------- attention HMMA, fp16 input ----------------
__global__ void __launch_bounds__(256, 1) attn_hmma() {
    extern __shared__ char sm[];
    __half* Qs = (__half*)sm;                       // 256*72
    __half* Ks = (__half*)(sm + 36864);             // 64*72
    __half* Vt = (__half*)(sm + 46080);             // 64*72
    const int b = blockIdx.x, h = blockIdx.y;
    const int tid = threadIdx.x, w = tid >> 5, lane = tid & 31;
    const __half* Qh = QKVh + ((size_t)(b*4 + h))*TT*64;
    const __half* Kh = Qh + PSTR;
    const __half* Vh = Kh + PSTR;

    {
        const uint4* q4 = (const uint4*)Qh;
#pragma unroll
        for (int i = 0; i < 8; i++) {
            int idx = tid + i*256;              // 0..2047
            int row = idx >> 3, q = idx & 7;
            *(uint4*)(Qs + row*QS + q*8) = q4[row*8 + q];
        }
    }
    __syncthreads();

    const int arow = (lane & 7) + (((lane >> 3) & 1) << 3);
    const int akoff = ((lane >> 4) & 1) * 8;
    unsigned aQ[2][4][4];
#pragma unroll
    for (int mt = 0; mt < 2; mt++) {
        unsigned abase = (unsigned)__cvta_generic_to_shared(Qs)
                       + (unsigned)(((w*32 + mt*16 + arow)*QS + akoff)*2);
#pragma unroll
        for (int kt = 0; kt < 4; kt++)
            ldsm4(aQ[mt][kt][0], aQ[mt][kt][1], aQ[mt][kt][2], aQ[mt][kt][3], abase + kt*32);
    }

    const unsigned bK = (unsigned)__cvta_generic_to_shared(Ks)
                      + (unsigned)((((lane & 7)*QS) + ((lane >> 3) & 1)*8)*2);
    const unsigned bV = (unsigned)__cvta_generic_to_shared(Vt)
                      + (unsigned)((((lane & 7)*QS) + ((lane >> 3) & 1)*8)*2);

    float oacc[2][8][4];
#pragma unroll
    for (int mt = 0; mt < 2; mt++)
#pragma unroll
        for (int nt = 0; nt < 8; nt++)
#pragma unroll
            for (int i = 0; i < 4; i++) oacc[mt][nt][i] = 0.f;
    float rs[2][2] = {{0.f,0.f},{0.f,0.f}};

    for (int kc = 0; kc < 4; kc++) {
        {
            const uint4* k4 = (const uint4*)(Kh + (size_t)kc*64*64);
#pragma unroll
            for (int i = 0; i < 2; i++) {
                int idx = tid + i*256;          // 0..511
                int row = idx >> 3, q = idx & 7;
                *(uint4*)(Ks + row*QS + q*8) = k4[row*8 + q];
            }
        }
#pragma unroll
        for (int i = 0; i < 16; i++) {
            int idx = tid + i*256;
            int key = idx >> 6, d = idx & 63;
            Vt[d*QS + key] = Vh[(size_t)(kc*64 + key)*64 + d];
        }
        __syncthreads();

        float sc[2][8][4];
#pragma unroll
        for (int mt = 0; mt < 2; mt++)
#pragma unroll
            for (int nt = 0; nt < 8; nt++)
#pragma unroll
                for (int i = 0; i < 4; i++) sc[mt][nt][i] = 0.f;
#pragma unroll
        for (int kt = 0; kt < 4; kt++) {
#pragma unroll
            for (int nt = 0; nt < 8; nt++) {
                unsigned b0, b1;
                ldsm2(b0, b1, bK + (unsigned)(nt*8*QS*2) + kt*32);
                mma_op(sc[0][nt], aQ[0][kt][0], aQ[0][kt][1], aQ[0][kt][2], aQ[0][kt][3], b0, b1);
                mma_op(sc[1][nt], aQ[1][kt][0], aQ[1][kt][1], aQ[1][kt][2], aQ[1][kt][3], b0, b1);
            }
        }

#pragma unroll
        for (int mt = 0; mt < 2; mt++)
#pragma unroll
            for (int nt = 0; nt < 8; nt++) {
                float p0 = __expf(sc[mt][nt][0] * 0.125f);
                float p1 = __expf(sc[mt][nt][1] * 0.125f);
                float p2 = __expf(sc[mt][nt][2] * 0.125f);
                float p3 = __expf(sc[mt][nt][3] * 0.125f);
                rs[mt][0] += p0 + p1;
                rs[mt][1] += p2 + p3;
                sc[mt][nt][0] = p0; sc[mt][nt][1] = p1;
                sc[mt][nt][2] = p2; sc[mt][nt][3] = p3;
            }

#pragma unroll
        for (int kt2 = 0; kt2 < 4; kt2++) {
            unsigned aP[2][4];
#pragma unroll
            for (int mt = 0; mt < 2; mt++) {
                aP[mt][0] = pack_h2(sc[mt][2*kt2][0],   sc[mt][2*kt2][1]);
                aP[mt][1] = pack_h2(sc[mt][2*kt2][2],   sc[mt][2*kt2][3]);
                aP[mt][2] = pack_h2(sc[mt][2*kt2+1][0], sc[mt][2*kt2+1][1]);
                aP[mt][3] = pack_h2(sc[mt][2*kt2+1][2], sc[mt][2*kt2+1][3]);
            }
#pragma unroll
            for (int nt = 0; nt < 8; nt++) {
                unsigned b0, b1;
                ldsm2(b0, b1, bV + (unsigned)(nt*8*QS*2) + kt2*32);
                mma_op(oacc[0][nt], aP[0][0], aP[0][1], aP[0][2], aP[0][3], b0, b1);
                mma_op(oacc[1][nt], aP[1][0], aP[1][1], aP[1][2], aP[1][3], b0, b1);
            }
        }
        __syncthreads();
    }

#pragma unroll
    for (int mt = 0; mt < 2; mt++)
#pragma unroll
        for (int j = 0; j < 2; j++) {
            rs[mt][j] += __shfl_xor_sync(0xffffffffu, rs[mt][j], 1);
            rs[mt][j] += __shfl_xor_sync(0xffffffffu, rs[mt][j], 2);
        }

    const int r = lane >> 2, c = lane & 3;
#pragma unroll
    for (int mt = 0; mt < 2; mt++) {
        float inv0 = 1.f / rs[mt][0];
        float inv1 = 1.f / rs[mt][1];
        int row0 = w*32 + mt*16 + r;
        int row1 = row0 + 8;
#pragma unroll
        for (int nt = 0; nt < 8; nt++) {
            int col = h*64 + nt*8 + 2*c;
            *(unsigned*)&CTXh[((size_t)(b*TT + row0))*HH + col] =
                pack_h2(oacc[mt][nt][0]*inv0, oacc[mt][nt][1]*inv0);
            *(unsigned*)&CTXh[((size_t)(b*TT + row1))*HH + col] =
                pack_h2(oacc[mt][nt][2]*inv1, oacc[mt][nt][3]*inv1);
        }
    }
}

// ---------------- final HMMA (verified) ----------------
__global__ void __launch_bounds__(256) final_hmma(const float* __restrict__ W2,
                                                  const float* __restrict__ b2p,
                                                  float* __restrict__ out) {
    extern __shared__ char sm[];
    __half* Xs   = (__half*)sm;
    __half* Wsm  = (__half*)(sm + 32*FS*2);
    float*  redm = (float*)(sm + 32*FS*2 + 256*FS*2);
    const int m0 = blockIdx.x * 32;
    const int tid = threadIdx.x, w = tid >> 5, lane = tid & 31;
    const int mt = w >> 2, nq = w & 3;

    float acc[8][4];
#pragma unroll
    for (int i = 0; i < 8; i++)
#pragma unroll
        for (int j = 0; j < 4; j++) acc[i][j] = 0.f;

    const int arow = (lane & 7) + (((lane >> 3) & 1) << 3);
    const int akoff = ((lane >> 4) & 1) * 8;
    const unsigned abase = (unsigned)__cvta_generic_to_shared(Xs)
                         + (unsigned)(((mt*16 + arow)*FS + akoff)*2);
    const unsigned bbase = (unsigned)__cvta_generic_to_shared(Wsm)
                         + (unsigned)((((nq*64 + (lane & 7))*FS) + ((lane >> 3) & 1)*8)*2);

    for (int ch = 0; ch < 4; ch++) {
        const __half* xsrc = (ch < 2) ? Lgh : CTXh;
        int kc = (ch & 1) * 128;
#pragma unroll
        for (int i = 0; i < 2; i++) {
            int idx = tid + i*256;
            int row = idx >> 4, q = idx & 15;
            *(uint4*)(Xs + row*FS + q*8) =
                *(const uint4*)(xsrc + (size_t)(m0+row)*256 + kc + q*8);
        }
#pragma unroll
        for (int i = 0; i < 16; i++) {
            int idx = tid + i*256;
            int row = idx >> 4, q = idx & 15;
            *(uint4*)(Wsm + row*FS + q*8) =
                *(const uint4*)(WfinH + (size_t)row*512 + ch*128 + q*8);
        }
        __syncthreads();
#pragma unroll
        for (int kt = 0; kt < 8; kt++) {
            unsigned a0,a1,a2,a3;
            ldsm4(a0,a1,a2,a3, abase + kt*32);
#pragma unroll
            for (int nt = 0; nt < 8; nt++) {
                unsigned b0,b1;
                ldsm2(b0,b1, bbase + (unsigned)(nt*8*FS*2) + kt*32);
                mma_op(acc[nt], a0,a1,a2,a3, b0,b1);
            }
        }
        __syncthreads();
    }

    const int r = lane >> 2, c = lane & 3;
    float s0 = 0.f, s1 = 0.f;
#pragma unroll
    for (int nt = 0; nt < 8; nt++) {
        int nn = nq*64 + nt*8 + 2*c;
        float bb0 = b1fw[nn], bb1v = b1fw[nn+1];
        float w20 = W2[nn],   w21 = W2[nn+1];
        s0 += w20*fmaxf(acc[nt][0] + bb0, 0.f) + w21*fmaxf(acc[nt][1] + bb1v, 0.f);
        s1 += w20*fmaxf(acc[nt][2] + bb0, 0.f) + w21*fmaxf(acc[nt][3] + bb1v, 0.f);
    }
    s0 += __shfl_xor_sync(0xffffffffu, s0, 1);
    s0 += __shfl_xor_sync(0xffffffffu, s0, 2);
    s1 += __shfl_xor_sync(0xffffffffu, s1, 1);
    s1 += __shfl_xor_sync(0xffffffffu, s1, 2);
    if ((lane & 3) == 0) {
        redm[nq*32 + mt*16 + r]     = s0;
        redm[nq*32 + mt*16 + 8 + r] = s1;
    }
    __syncthreads();
    if (tid < 32)
        out[m0 + tid] = b2p[0] + redm[tid] + redm[32 + tid] + redm[64 + tid] + redm[96 + tid];
}

// ---------------- launch ----------------
extern "C" void kernel_launch(void* const* d_in, const int* in_sizes, int n_in,
                              void* d_out, int out_size) {
    (void)in_sizes; (void)n_in; (void)out_size;
    const float* F     = (const float*)d_in[0];
    const float* Wih0  = (const float*)d_in[1];
    const float* Whh0  = (const float*)d_in[2];
    const float* bih0  = (const float*)d_in[3];
    const float* bhh0  = (const float*)d_in[4];
    const float* Wih1  = (const float*)d_in[5];
    const float* Whh1  = (const float*)d_in[6];
    const float* bih1  = (const float*)d_in[7];
    const float* bhh1  = (const float*)d_in[8];
    const float* Winp  = (const float*)d_in[9];
    const float* binp  = (const float*)d_in[10];
    const float* Wop   = (const float*)d_in[11];
    const float* bop   = (const float*)d_in[12];
    const float* W1    = (const float*)d_in[13];
    const float* b1    = (const float*)d_in[14];
    const float* W2    = (const float*)d_in[15];
    const float* b2    = (const float*)d_in[16];
    float* out = (float*)d_out;

    const int SCAN_SMEM = 51968;
    const int QKV_SMEM  = (128*XS + 64*XS)*2;
    const int ATT_SMEM  = 256*QS*2 + 64*QS*2 + 64*QS*2;
    const int FIN_SMEM  = (32*FS + 256*FS)*2 + 4*32*4;
    cudaFuncSetAttribute(scan_kernel, cudaFuncAttributeMaxDynamicSharedMemorySize, SCAN_SMEM);
    cudaFuncSetAttribute(qkv_hmma,    cudaFuncAttributeMaxDynamicSharedMemorySize, QKV_SMEM);
    cudaFuncSetAttribute(attn_hmma,   cudaFuncAttributeMaxDynamicSharedMemorySize, ATT_SMEM);
    cudaFuncSetAttribute(final_hmma,  cudaFuncAttributeMaxDynamicSharedMemorySize, FIN_SMEM);

    prep_frag<<<4544, 256>>>(Wih0, Whh0, Wih1, Whh1, W1, Winp);
    prep_wcomb<<<256, 256>>>(W1, Wop);
    prep_b1f<<<1, 256>>>(b1, bop, W1);
    scan_kernel<<<128, 512, SCAN_SMEM>>>(F, bih0, bhh0, bih1, bhh1, b1, W2, b2);
    qkv_hmma<<<dim3(1024, 12), 256, QKV_SMEM>>>(binp);
    attn_hmma<<<dim3(512, 4), 256, ATT_SMEM>>>();
    final_hmma<<<4096, 256, FIN_SMEM>>>(W2, b2, out);
}

// round 16
// speedup vs baseline: 1.8826x; 1.0205x over previous
#include <cuda_runtime.h>
#include <cuda_fp16.h>
#include <math.h>

#define BATCH 512
#define TT    256
#define DD    32
#define HH    256
#define M_TOTAL (BATCH*TT)
#define PSTR  (BATCH*4*TT*64)

// scan config: 32 clusters x 4 CTAs, 16 rows/cluster, 64 neurons/CTA
#define CL   4
#define RPB  16
#define K0T  19
#define K1T  32
#define KFT  16
#define SA   1080
#define GSTR 17
#define XS   264
#define QS   72
#define FS   136

// ---------------- static device scratch ----------------
__device__ __half W0f[K0T*64*256];
__device__ __half W1f[K1T*64*256];
__device__ __half WFf[KFT*16*256];
__device__ __half WinpH[768*256];
__device__ __half WfinH[256*512];
__device__ float  b1fw[256];
__device__ __half Lgh[M_TOTAL*HH];
__device__ __half CTXh[M_TOTAL*HH];
__device__ __half QKVh[3*PSTR];

__device__ __forceinline__ float sigf(float x) { return 1.f / (1.f + __expf(-x)); }
__device__ __forceinline__ float tanh_f(float x) {
    x = fmaxf(fminf(x, 30.f), -30.f);
    float z = __expf(-2.f * x);
    return (1.f - z) / (1.f + z);
}
__device__ __forceinline__ void ldsm4(unsigned &r0, unsigned &r1, unsigned &r2, unsigned &r3, unsigned addr) {
    asm volatile("ldmatrix.sync.aligned.m8n8.x4.shared.b16 {%0,%1,%2,%3}, [%4];"
                 : "=r"(r0),"=r"(r1),"=r"(r2),"=r"(r3) : "r"(addr));
}
__device__ __forceinline__ void ldsm2(unsigned &r0, unsigned &r1, unsigned addr) {
    asm volatile("ldmatrix.sync.aligned.m8n8.x2.shared.b16 {%0,%1}, [%2];"
                 : "=r"(r0),"=r"(r1) : "r"(addr));
}
__device__ __forceinline__ void mma_op(float* c, unsigned a0, unsigned a1, unsigned a2, unsigned a3,
                                       unsigned b0, unsigned b1) {
    asm volatile("mma.sync.aligned.m16n8k16.row.col.f32.f16.f16.f32 "
        "{%0,%1,%2,%3}, {%4,%5,%6,%7}, {%8,%9}, {%0,%1,%2,%3};"
        : "+f"(c[0]), "+f"(c[1]), "+f"(c[2]), "+f"(c[3])
        : "r"(a0), "r"(a1), "r"(a2), "r"(a3), "r"(b0), "r"(b1));
}
__device__ __forceinline__ unsigned pack_h2(float a, float b) {
    __half2 h = __floats2half2_rn(a, b);
    return *(unsigned*)&h;
}
__device__ __forceinline__ void cluster_sync_() {
    asm volatile("barrier.cluster.arrive.aligned;\n\tbarrier.cluster.wait.aligned;" ::: "memory");
}
__device__ __forceinline__ void st_cluster_u32(unsigned laddr, unsigned rank, unsigned val) {
    unsigned ra;
    asm volatile("mapa.shared::cluster.u32 %0, %1, %2;" : "=r"(ra) : "r"(laddr), "r"(rank));
    asm volatile("st.shared::cluster.u32 [%0], %1;" :: "r"(ra), "r"(val) : "memory");
}

// ---------------- prep (verified) ----------------
__global__ void prep_frag(const float* __restrict__ Wih0, const float* __restrict__ Whh0,
                          const float* __restrict__ Wih1, const float* __restrict__ Whh1,
                          const float* __restrict__ W1,   const float* __restrict__ Winp) {
    int i = blockIdx.x * 256 + threadIdx.x;
    const int E0 = K0T*64*256;
    const int E1 = E0 + K1T*64*256;
    const int E2 = E1 + KFT*16*256;
    const int E3 = E2 + 768*256;
    const int E4 = E3 + 65536;
    if (i < E0) {
        int q = i & 7, lane = (i >> 3) & 31, tile = i >> 8;
        int mt = tile / K0T, kt = tile - mt * K0T;
        int r = lane >> 2, c = lane & 3;
        int dm = r + ((q >> 1) & 1) * 8;
        int dk = 2*c + (q & 1) + ((q >= 4) ? 8 : 0);
        int m = mt*16 + dm, k = kt*16 + dk;
        float v = 0.f;
        if (k < 33) v = Wih0[m*33 + k];
        else if (k >= 48) v = Whh0[m*256 + (k - 48)];
        W0f[i] = __float2half(v);
    } else if (i < E1) {
        int e = i - E0;
        int q = e & 7, lane = (e >> 3) & 31, tile = e >> 8;
        int mt = tile >> 5, kt = tile & 31;
        int r = lane >> 2, c = lane & 3;
        int dm = r + ((q >> 1) & 1) * 8;
        int dk = 2*c + (q & 1) + ((q >= 4) ? 8 : 0);
        int m = mt*16 + dm, k = kt*16 + dk;
        float v = (k < 256) ? Wih1[m*256 + k] : Whh1[m*256 + (k - 256)];
        W1f[e] = __float2half(v);
    } else if (i < E2) {
        int e = i - E1;
        int q = e & 7, lane = (e >> 3) & 31, tile = e >> 8;
        int mt = tile >> 4, kt = tile & 15;
        int r = lane >> 2, c = lane & 3;
        int dm = r + ((q >> 1) & 1) * 8;
        int dk = 2*c + (q & 1) + ((q >= 4) ? 8 : 0);
        int m = mt*16 + dm, k = kt*16 + dk;
        WFf[e] = __float2half(W1[m*512 + k] + W1[m*512 + 256 + k]);
    } else if (i < E3) {
        int e = i - E2;
        WinpH[e] = __float2half(Winp[e]);
    } else if (i < E4) {
        int e = i - E3; int r = e >> 8, k = e & 255;
        WfinH[r*512 + k] = __float2half(W1[r*512 + k]);
    }
}

__global__ void prep_wcomb(const float* __restrict__ W1, const float* __restrict__ Wop) {
    int r = blockIdx.x, m = threadIdx.x;
    float s = 0.f;
    for (int k = 0; k < 256; k++) s += W1[r*512 + 256 + k] * Wop[k*256 + m];
    WfinH[r*512 + 256 + m] = __float2half(s);
}

__global__ void prep_b1f(const float* __restrict__ b1, const float* __restrict__ bop,
                         const float* __restrict__ W1) {
    int r = threadIdx.x;
    float s = b1[r];
    for (int k = 0; k < 256; k++) s += bop[k] * W1[r*512 + 256 + k];
    b1fw[r] = s;
}

// ---------------- scan warp GEMM, N=16 (verified) ----------------
template<int KT, int SPLIT>
__device__ __forceinline__ void gemm_warp(const __half* __restrict__ Wg, int mtA, int mtC,
                                          unsigned actb, int bstr, unsigned extra,
                                          float* __restrict__ gs, int lane) {
    const int r = lane >> 2, c2 = (lane & 3) * 2;
    float acc0[4] = {0.f,0.f,0.f,0.f};
    float acc1[4] = {0.f,0.f,0.f,0.f};
    const uint4* Ap = (const uint4*)Wg + (size_t)mtA*KT*32 + lane;
    const int brow = (lane & 7) + ((lane >> 4) << 3);
    const int bkoff = ((lane >> 3) & 1) * 8;
    const unsigned baddr = actb + (unsigned)((brow*bstr + bkoff) * 2);
#pragma unroll
    for (int kt = 0; kt < KT; kt++) {
        uint4 A = Ap[kt*32];
        unsigned b00, b01, b10, b11;
        unsigned addr = baddr + (unsigned)(kt*32) + ((kt >= SPLIT) ? extra : 0u);
        ldsm4(b00, b01, b10, b11, addr);
        mma_op(acc0, A.x, A.y, A.z, A.w, b00, b01);
        mma_op(acc1, A.x, A.y, A.z, A.w, b10, b11);
    }
    const int m0 = mtC*16;
    float* g0 = gs + (m0 + r)*GSTR + c2;
    float* g1 = gs + (m0 + 8 + r)*GSTR + c2;
    g0[0] = acc0[0]; g0[1] = acc0[1];
    g1[0] = acc0[2]; g1[1] = acc0[3];
    g0[8] = acc1[0]; g0[9] = acc1[1];
    g1[8] = acc1[2]; g1[9] = acc1[3];
}

// ---------------- clustered scan: 128 CTAs (32 clusters x 4), 512 thr ----------------
extern __shared__ char smem_raw[];

__global__ void __launch_bounds__(512, 1) __cluster_dims__(CL, 1, 1)
scan_kernel(const float* __restrict__ F,
            const float* __restrict__ bih0, const float* __restrict__ bhh0,
            const float* __restrict__ bih1, const float* __restrict__ bhh1,
            const float* __restrict__ b1, const float* __restrict__ W2,
            const float* __restrict__ b2p)
{
    __half* act  = (__half*)smem_raw;                 // 16*1080*2 = 34560
    float*  gs   = (float*)(smem_raw + 34560);        // 256*17*4  = 17408
    float*  pdex = (float*)(smem_raw + 51968);        // 64*4 = 256 -> 52224

    const int tid = threadIdx.x;
    const int w = tid >> 5, lane = tid & 31;
    unsigned crank; asm("mov.u32 %0, %%cluster_ctarank;" : "=r"(crank));
    const int b0r = (blockIdx.x >> 2) * RPB;
    const int nbase = (int)crank * 64;
    const int ar = w;
    const int u  = lane * 2;
    const int ng = nbase + u;

    const unsigned a_b  = (unsigned)__cvta_generic_to_shared(act);
    const unsigned pd_b = (unsigned)__cvta_generic_to_shared(pdex);

    const int gq = w >> 2, qq = w & 3;
    const int mtA01 = gq*16 + (int)crank*4 + qq;

    float bi0[2][4], bi1[2][4];
#pragma unroll
    for (int j = 0; j < 2; j++)
#pragma unroll
        for (int g = 0; g < 4; g++) {
            bi0[j][g] = bih0[g*256 + ng + j] + bhh0[g*256 + ng + j];
            bi1[j][g] = bih1[g*256 + ng + j] + bhh1[g*256 + ng + j];
        }
    float fw2v[2], fb1v[2];
#pragma unroll
    for (int j = 0; j < 2; j++) {
        int gu = (int)crank*64 + u + j;
        fw2v[j] = W2[gu]; fb1v[j] = b1[gu];
    }
    const float b2v = b2p[0];
    float c1v[2] = {0.f, 0.f}, c2v[2] = {0.f, 0.f};

    const __half hz = __float2half(0.f);
    for (int i = tid; i < RPB*SA; i += 512) act[i] = hz;
    cluster_sync_();

    for (int t = 0; t < TT; t++) {
        const int hb = t & 1;
        const unsigned ext0 = (unsigned)(((t + 1) & 1) * 512);
        const unsigned ext1 = (unsigned)(1024 - hb*1024);
        const unsigned base1 = a_b + (unsigned)((48 + hb*256) * 2);
        const unsigned baseF = a_b + (unsigned)((560 + hb*256) * 2);

        {
            int row = tid >> 5, kx = tid & 31;
            act[row*SA + kx] = __float2half(F[(size_t)(b0r + row)*(TT*DD) + t*DD + kx]);
        }
        __syncthreads();

        gemm_warp<K0T, 3>(W0f, mtA01, w, a_b, SA, ext0, gs, lane);
        __syncthreads();

        // L0 activation
        {
            float h1p[2];
#pragma unroll
            for (int j = 0; j < 2; j++) {
                float gi = gs[(      u + j)*GSTR + ar] + bi0[j][0];
                float gf = gs[( 64 + u + j)*GSTR + ar] + bi0[j][1];
                float gG = gs[(128 + u + j)*GSTR + ar] + bi0[j][2];
                float go = gs[(192 + u + j)*GSTR + ar] + bi0[j][3];
                c1v[j] = sigf(gf)*c1v[j] + sigf(gi)*tanh_f(gG);
                h1p[j] = sigf(go)*tanh_f(c1v[j]);
            }
            unsigned hv = pack_h2(h1p[0], h1p[1]);
            unsigned off = a_b + (unsigned)((ar*SA + 48 + hb*256 + ng) * 2);
#pragma unroll
            for (unsigned rk = 0; rk < CL; rk++) st_cluster_u32(off, rk, hv);
        }
        cluster_sync_();

        gemm_warp<K1T, 16>(W1f, mtA01, w, base1, SA, ext1, gs, lane);
        __syncthreads();

        // L1 activation + Lgh
        {
            float h2p[2];
#pragma unroll
            for (int j = 0; j < 2; j++) {
                float gi = gs[(      u + j)*GSTR + ar] + bi1[j][0];
                float gf = gs[( 64 + u + j)*GSTR + ar] + bi1[j][1];
                float gG = gs[(128 + u + j)*GSTR + ar] + bi1[j][2];
                float go = gs[(192 + u + j)*GSTR + ar] + bi1[j][3];
                c2v[j] = sigf(gf)*c2v[j] + sigf(gi)*tanh_f(gG);
                h2p[j] = sigf(go)*tanh_f(c2v[j]);
            }
            unsigned hv = pack_h2(h2p[0], h2p[1]);
            unsigned off = a_b + (unsigned)((ar*SA + 560 + hb*256 + ng) * 2);
#pragma unroll
            for (unsigned rk = 0; rk < CL; rk++) st_cluster_u32(off, rk, hv);
            *(unsigned*)&Lgh[(size_t)(b0r + ar)*(TT*HH) + (size_t)t*HH + ng] = hv;
        }
        cluster_sync_();

        // FC distributed: warp w -> m-quarter q=w&3, k-slice ks=w>>2
        {
            int q = w & 3, ks = w >> 2;
            gemm_warp<4, 99>(WFf, ((int)crank*4 + q)*4 + ks, ks*4 + q,
                             baseF + (unsigned)(ks*128), SA, 0u, gs, lane);
        }
        __syncthreads();

        // local pd partial over this CTA's 64 units
        {
            float v = 0.f;
#pragma unroll
            for (int j = 0; j < 2; j++) {
                float s = fb1v[j];
#pragma unroll
                for (int ks2 = 0; ks2 < 4; ks2++) s += gs[(ks2*64 + u + j)*GSTR + ar];
                v += fw2v[j] * fmaxf(s, 0.f);
            }
#pragma unroll
            for (int off = 16; off > 0; off >>= 1)
                v += __shfl_down_sync(0xffffffffu, v, off);
            if (lane == 0) {
                unsigned pv = __float_as_uint(v);
                unsigned off2 = pd_b + (unsigned)((ar*4 + (int)crank) * 4);
#pragma unroll
                for (unsigned rk = 0; rk < CL; rk++) st_cluster_u32(off2, rk, pv);
            }
        }
        cluster_sync_();
        if (tid < 16) {
            float s = b2v + pdex[tid*4+0] + pdex[tid*4+1] + pdex[tid*4+2] + pdex[tid*4+3];
            act[tid*SA + 32] = __float2half(s);
        }
    }
}

// ---------------- qkv HMMA GEMM, fp16 output (verified) ----------------
__global__ void __launch_bounds__(256) qkv_hmma(const float* __restrict__ binp) {
    extern __shared__ char sm[];
    __half* Xs  = (__half*)sm;
    __half* Wsh = (__half*)(sm + 128*XS*2);
    const int m0 = blockIdx.x * 128;
    const int n0 = blockIdx.y * 64;
    const int tid = threadIdx.x, w = tid >> 5, lane = tid & 31;

    {
        const uint4* src = (const uint4*)(Lgh + (size_t)m0*256);
#pragma unroll
        for (int i = 0; i < 16; i++) {
            int idx = tid + i*256;
            int row = idx >> 5, q = idx & 31;
            *(uint4*)(Xs + row*XS + q*8) = src[row*32 + q];
        }
        const uint4* wsrc = (const uint4*)(WinpH + (size_t)n0*256);
#pragma unroll
        for (int i = 0; i < 8; i++) {
            int idx = tid + i*256;
            int row = idx >> 5, q = idx & 31;
            *(uint4*)(Wsh + row*XS + q*8) = wsrc[row*32 + q];
        }
    }
    __syncthreads();

    float acc[8][4];
#pragma unroll
    for (int i = 0; i < 8; i++)
#pragma unroll
        for (int j = 0; j < 4; j++) acc[i][j] = 0.f;

    const int arow = (lane & 7) + (((lane >> 3) & 1) << 3);
    const int akoff = ((lane >> 4) & 1) * 8;
    const unsigned abase = (unsigned)__cvta_generic_to_shared(Xs)
                         + (unsigned)(((w*16 + arow)*XS + akoff)*2);
    const unsigned bbase = (unsigned)__cvta_generic_to_shared(Wsh)
                         + (unsigned)((((lane & 7)*XS) + ((lane >> 3) & 1)*8)*2);

#pragma unroll
    for (int kt = 0; kt < 16; kt++) {
        unsigned a0,a1,a2,a3;
        ldsm4(a0,a1,a2,a3, abase + kt*32);
#pragma unroll
        for (int nt = 0; nt < 8; nt++) {
            unsigned b0,b1;
            ldsm2(b0,b1, bbase + (unsigned)(nt*8*XS*2) + kt*32);
            mma_op(acc[nt], a0,a1,a2,a3, b0,b1);
        }
    }

    const int r = lane >> 2, c = lane & 3;
    const int m1 = m0 + w*16 + r, m2 = m1 + 8;
    const int bb1 = m1 >> 8, tt1 = m1 & 255;
    const int bb2 = m2 >> 8, tt2 = m2 & 255;
#pragma unroll
    for (int nt = 0; nt < 8; nt++) {
        int nn = n0 + nt*8 + 2*c;
        float bi0 = binp[nn], bi1 = binp[nn+1];
        int part = nn >> 8, head = (nn >> 6) & 3, d = nn & 63;
        __half* d1 = QKVh + ((size_t)((part*BATCH + bb1)*4 + head)*TT + tt1)*64 + d;
        __half* d2 = QKVh + ((size_t)((part*BATCH + bb2)*4 + head)*TT + tt2)*64 + d;
        *(unsigned*)d1 = pack_h2(acc[nt][0]+bi0, acc[nt][1]+bi1);
        *(unsigned*)d2 = pack_h2(acc[nt][2]+bi0, acc[nt][3]+bi1);
    }
}

// ---------------- attention HMMA, fp16 input (verified) ----------------
__global__ void __launch_bounds__(256, 1) attn_hmma() {
    extern __shared__ char sm[];
    __half* Qs = (__half*)sm;
    __half* Ks = (__half*)(sm + 36864);
    __half* Vt = (__half*)(sm + 46080);
    const int b = blockIdx.x, h = blockIdx.y;
    const int tid = threadIdx.x, w = tid >> 5, lane = tid & 31;
    const __half* Qh = QKVh + ((size_t)(b*4 + h))*TT*64;
    const __half* Kh = Qh + PSTR;
    const __half* Vh = Kh + PSTR;

    {
        const uint4* q4 = (const uint4*)Qh;
#pragma unroll
        for (int i = 0; i < 8; i++) {
            int idx = tid + i*256;
            int row = idx >> 3, q = idx & 7;
            *(uint4*)(Qs + row*QS + q*8) = q4[row*8 + q];
        }
    }
    __syncthreads();

    const int arow = (lane & 7) + (((lane >> 3) & 1) << 3);
    const int akoff = ((lane >> 4) & 1) * 8;
    unsigned aQ[2][4][4];
#pragma unroll
    for (int mt = 0; mt < 2; mt++) {
        unsigned abase = (unsigned)__cvta_generic_to_shared(Qs)
                       + (unsigned)(((w*32 + mt*16 + arow)*QS + akoff)*2);
#pragma unroll
        for (int kt = 0; kt < 4; kt++)
            ldsm4(aQ[mt][kt][0], aQ[mt][kt][1], aQ[mt][kt][2], aQ[mt][kt][3], abase + kt*32);
    }

    const unsigned bK = (unsigned)__cvta_generic_to_shared(Ks)
                      + (unsigned)((((lane & 7)*QS) + ((lane >> 3) & 1)*8)*2);
    const unsigned bV = (unsigned)__cvta_generic_to_shared(Vt)
                      + (unsigned)((((lane & 7)*QS) + ((lane >> 3) & 1)*8)*2);

    float oacc[2][8][4];
#pragma unroll
    for (int mt = 0; mt < 2; mt++)
#pragma unroll
        for (int nt = 0; nt < 8; nt++)
#pragma unroll
            for (int i = 0; i < 4; i++) oacc[mt][nt][i] = 0.f;
    float rs[2][2] = {{0.f,0.f},{0.f,0.f}};

    for (int kc = 0; kc < 4; kc++) {
        {
            const uint4* k4 = (const uint4*)(Kh + (size_t)kc*64*64);
#pragma unroll
            for (int i = 0; i < 2; i++) {
                int idx = tid + i*256;
                int row = idx >> 3, q = idx & 7;
                *(uint4*)(Ks + row*QS + q*8) = k4[row*8 + q];
            }
        }
#pragma unroll
        for (int i = 0; i < 16; i++) {
            int idx = tid + i*256;
            int key = idx >> 6, d = idx & 63;
            Vt[d*QS + key] = Vh[(size_t)(kc*64 + key)*64 + d];
        }
        __syncthreads();

        float sc[2][8][4];
#pragma unroll
        for (int mt = 0; mt < 2; mt++)
#pragma unroll
            for (int nt = 0; nt < 8; nt++)
#pragma unroll
                for (int i = 0; i < 4; i++) sc[mt][nt][i] = 0.f;
#pragma unroll
        for (int kt = 0; kt < 4; kt++) {
#pragma unroll
            for (int nt = 0; nt < 8; nt++) {
                unsigned b0, b1;
                ldsm2(b0, b1, bK + (unsigned)(nt*8*QS*2) + kt*32);
                mma_op(sc[0][nt], aQ[0][kt][0], aQ[0][kt][1], aQ[0][kt][2], aQ[0][kt][3], b0, b1);
                mma_op(sc[1][nt], aQ[1][kt][0], aQ[1][kt][1], aQ[1][kt][2], aQ[1][kt][3], b0, b1);
            }
        }

#pragma unroll
        for (int mt = 0; mt < 2; mt++)
#pragma unroll
            for (int nt = 0; nt < 8; nt++) {
                float p0 = __expf(sc[mt][nt][0] * 0.125f);
                float p1 = __expf(sc[mt][nt][1] * 0.125f);
                float p2 = __expf(sc[mt][nt][2] * 0.125f);
                float p3 = __expf(sc[mt][nt][3] * 0.125f);
                rs[mt][0] += p0 + p1;
                rs[mt][1] += p2 + p3;
                sc[mt][nt][0] = p0; sc[mt][nt][1] = p1;
                sc[mt][nt][2] = p2; sc[mt][nt][3] = p3;
            }

#pragma unroll
        for (int kt2 = 0; kt2 < 4; kt2++) {
            unsigned aP[2][4];
#pragma unroll
            for (int mt = 0; mt < 2; mt++) {
                aP[mt][0] = pack_h2(sc[mt][2*kt2][0],   sc[mt][2*kt2][1]);
                aP[mt][1] = pack_h2(sc[mt][2*kt2][2],   sc[mt][2*kt2][3]);
                aP[mt][2] = pack_h2(sc[mt][2*kt2+1][0], sc[mt][2*kt2+1][1]);
                aP[mt][3] = pack_h2(sc[mt][2*kt2+1][2], sc[mt][2*kt2+1][3]);
            }
#pragma unroll
            for (int nt = 0; nt < 8; nt++) {
                unsigned b0, b1;
                ldsm2(b0, b1, bV + (unsigned)(nt*8*QS*2) + kt2*32);
                mma_op(oacc[0][nt], aP[0][0], aP[0][1], aP[0][2], aP[0][3], b0, b1);
                mma_op(oacc[1][nt], aP[1][0], aP[1][1], aP[1][2], aP[1][3], b0, b1);
            }
        }
        __syncthreads();
    }

#pragma unroll
    for (int mt = 0; mt < 2; mt++)
#pragma unroll
        for (int j = 0; j < 2; j++) {
            rs[mt][j] += __shfl_xor_sync(0xffffffffu, rs[mt][j], 1);
            rs[mt][j] += __shfl_xor_sync(0xffffffffu, rs[mt][j], 2);
        }

    const int r = lane >> 2, c = lane & 3;
#pragma unroll
    for (int mt = 0; mt < 2; mt++) {
        float inv0 = 1.f / rs[mt][0];
        float inv1 = 1.f / rs[mt][1];
        int row0 = w*32 + mt*16 + r;
        int row1 = row0 + 8;
#pragma unroll
        for (int nt = 0; nt < 8; nt++) {
            int col = h*64 + nt*8 + 2*c;
            *(unsigned*)&CTXh[((size_t)(b*TT + row0))*HH + col] =
                pack_h2(oacc[mt][nt][0]*inv0, oacc[mt][nt][1]*inv0);
            *(unsigned*)&CTXh[((size_t)(b*TT + row1))*HH + col] =
                pack_h2(oacc[mt][nt][2]*inv1, oacc[mt][nt][3]*inv1);
        }
    }
}

// ---------------- final HMMA: 64 rows/block, 512 threads ----------------
__global__ void __launch_bounds__(512) final_hmma(const float* __restrict__ W2,
                                                  const float* __restrict__ b2p,
                                                  float* __restrict__ out) {
    extern __shared__ char sm[];
    __half* Xs   = (__half*)sm;                        // 64*136*2 = 17408
    __half* Wsm  = (__half*)(sm + 64*FS*2);            // 256*136*2 = 69632
    float*  redm = (float*)(sm + 64*FS*2 + 256*FS*2);  // 4*64*4 = 1024
    const int m0 = blockIdx.x * 64;
    const int tid = threadIdx.x, w = tid >> 5, lane = tid & 31;
    const int mt = w >> 2, nq = w & 3;

    float acc[8][4];
#pragma unroll
    for (int i = 0; i < 8; i++)
#pragma unroll
        for (int j = 0; j < 4; j++) acc[i][j] = 0.f;

    const int arow = (lane & 7) + (((lane >> 3) & 1) << 3);
    const int akoff = ((lane >> 4) & 1) * 8;
    const unsigned abase = (unsigned)__cvta_generic_to_shared(Xs)
                         + (unsigned)(((mt*16 + arow)*FS + akoff)*2);
    const unsigned bbase = (unsigned)__cvta_generic_to_shared(Wsm)
                         + (unsigned)((((nq*64 + (lane & 7))*FS) + ((lane >> 3) & 1)*8)*2);

    for (int ch = 0; ch < 4; ch++) {
        const __half* xsrc = (ch < 2) ? Lgh : CTXh;
        int kc = (ch & 1) * 128;
#pragma unroll
        for (int i = 0; i < 2; i++) {
            int idx = tid + i*512;                 // 1024 uint4 (64 rows x 16)
            int row = idx >> 4, q = idx & 15;
            *(uint4*)(Xs + row*FS + q*8) =
                *(const uint4*)(xsrc + (size_t)(m0+row)*256 + kc + q*8);
        }
#pragma unroll
        for (int i = 0; i < 8; i++) {              // FIX: was 4 — staged only half of Wsm
            int idx = tid + i*512;                 // 4096 uint4 (256 rows x 16)
            int row = idx >> 4, q = idx & 15;
            *(uint4*)(Wsm + row*FS + q*8) =
                *(const uint4*)(WfinH + (size_t)row*512 + ch*128 + q*8);
        }
        __syncthreads();
#pragma unroll
        for (int kt = 0; kt < 8; kt++) {
            unsigned a0,a1,a2,a3;
            ldsm4(a0,a1,a2,a3, abase + kt*32);
#pragma unroll
            for (int nt = 0; nt < 8; nt++) {
                unsigned b0,b1;
                ldsm2(b0,b1, bbase + (unsigned)(nt*8*FS*2) + kt*32);
                mma_op(acc[nt], a0,a1,a2,a3, b0,b1);
            }
        }
        __syncthreads();
    }

    const int r = lane >> 2, c = lane & 3;
    float s0 = 0.f, s1 = 0.f;
#pragma unroll
    for (int nt = 0; nt < 8; nt++) {
        int nn = nq*64 + nt*8 + 2*c;
        float bb0 = b1fw[nn], bb1v = b1fw[nn+1];
        float w20 = W2[nn],   w21 = W2[nn+1];
        s0 += w20*fmaxf(acc[nt][0] + bb0, 0.f) + w21*fmaxf(acc[nt][1] + bb1v, 0.f);
        s1 += w20*fmaxf(acc[nt][2] + bb0, 0.f) + w21*fmaxf(acc[nt][3] + bb1v, 0.f);
    }
    s0 += __shfl_xor_sync(0xffffffffu, s0, 1);
    s0 += __shfl_xor_sync(0xffffffffu, s0, 2);
    s1 += __shfl_xor_sync(0xffffffffu, s1, 1);
    s1 += __shfl_xor_sync(0xffffffffu, s1, 2);
    if ((lane & 3) == 0) {
        redm[nq*64 + mt*16 + r]     = s0;
        redm[nq*64 + mt*16 + 8 + r] = s1;
    }
    __syncthreads();
    if (tid < 64)
        out[m0 + tid] = b2p[0] + redm[tid] + redm[64 + tid] + redm[128 + tid] + redm[192 + tid];
}

// ---------------- launch ----------------
extern "C" void kernel_launch(void* const* d_in, const int* in_sizes, int n_in,
                              void* d_out, int out_size) {
    (void)in_sizes; (void)n_in; (void)out_size;
    const float* F     = (const float*)d_in[0];
    const float* Wih0  = (const float*)d_in[1];
    const float* Whh0  = (const float*)d_in[2];
    const float* bih0  = (const float*)d_in[3];
    const float* bhh0  = (const float*)d_in[4];
    const float* Wih1  = (const float*)d_in[5];
    const float* Whh1  = (const float*)d_in[6];
    const float* bih1  = (const float*)d_in[7];
    const float* bhh1  = (const float*)d_in[8];
    const float* Winp  = (const float*)d_in[9];
    const float* binp  = (const float*)d_in[10];
    const float* Wop   = (const float*)d_in[11];
    const float* bop   = (const float*)d_in[12];
    const float* W1    = (const float*)d_in[13];
    const float* b1    = (const float*)d_in[14];
    const float* W2    = (const float*)d_in[15];
    const float* b2    = (const float*)d_in[16];
    float* out = (float*)d_out;

    const int SCAN_SMEM = 52224;
    const int QKV_SMEM  = (128*XS + 64*XS)*2;
    const int ATT_SMEM  = 256*QS*2 + 64*QS*2 + 64*QS*2;
    const int FIN_SMEM  = 64*FS*2 + 256*FS*2 + 1024;
    cudaFuncSetAttribute(scan_kernel, cudaFuncAttributeMaxDynamicSharedMemorySize, SCAN_SMEM);
    cudaFuncSetAttribute(qkv_hmma,    cudaFuncAttributeMaxDynamicSharedMemorySize, QKV_SMEM);
    cudaFuncSetAttribute(attn_hmma,   cudaFuncAttributeMaxDynamicSharedMemorySize, ATT_SMEM);
    cudaFuncSetAttribute(final_hmma,  cudaFuncAttributeMaxDynamicSharedMemorySize, FIN_SMEM);

    prep_frag<<<4544, 256>>>(Wih0, Whh0, Wih1, Whh1, W1, Winp);
    prep_wcomb<<<256, 256>>>(W1, Wop);
    prep_b1f<<<1, 256>>>(b1, bop, W1);
    scan_kernel<<<128, 512, SCAN_SMEM>>>(F, bih0, bhh0, bih1, bhh1, b1, W2, b2);
    qkv_hmma<<<dim3(1024, 12), 256, QKV_SMEM>>>(binp);
    attn_hmma<<<dim3(512, 4), 256, ATT_SMEM>>>();
    final_hmma<<<2048, 512, FIN_SMEM>>>(W2, b2, out);
}